// round 2
// baseline (speedup 1.0000x reference)
#include <cuda_runtime.h>
#include <cuda_bf16.h>

typedef unsigned long long ull;

// Problem dims
#define B_   16
#define NC_  31
#define NXL  256
#define NYL  256
#define NO_  3
#define KXL  17
#define KYL  17
#define NG_  (NO_ * NC_)   // 93
#define WIN_ 9

// Compact weights: per (o,c) group a 9x9 tile of broadcast float2 pairs + origin
__device__ float2 g_w2[NG_ * WIN_ * WIN_];
__device__ int    g_kx0[NG_];
__device__ int    g_ky0[NG_];

// ---------------------------------------------------------------------------
// Prep: decode locations, find window origin per group, scatter relu(values)
// as broadcast (v,v) pairs. Single block; syncthreads orders phases.
// ---------------------------------------------------------------------------
__global__ void prep_kernel(const float* __restrict__ vk,
                            const int* __restrict__ loc, int nloc) {
    int tid = threadIdx.x;
    for (int i = tid; i < NG_; i += blockDim.x) {
        g_kx0[i] = 1 << 30;
        g_ky0[i] = 1 << 30;
    }
    __syncthreads();
    for (int i = tid; i < nloc; i += blockDim.x) {
        int idx = loc[i];
        int ky = idx % KYL; int t = idx / KYL;
        int kx = t % KXL;   t /= KXL;
        int g = t;  // o*NC_+c
        atomicMin(&g_kx0[g], kx);
        atomicMin(&g_ky0[g], ky);
    }
    __syncthreads();
    for (int i = tid; i < nloc; i += blockDim.x) {
        int idx = loc[i];
        float v = vk[i];
        v = v > 0.0f ? v : 0.0f;  // ReLU
        int ky = idx % KYL; int t = idx / KYL;
        int kx = t % KXL;   t /= KXL;
        int g = t;
        g_w2[g * (WIN_ * WIN_) + (kx - g_kx0[g]) * WIN_ + (ky - g_ky0[g])] =
            make_float2(v, v);
    }
}

// ---------------------------------------------------------------------------
// Main conv. Block = 256 threads, output tile 64x64 per (b, o).
// Thread: tx = tid&7 (8-col group), ty = tid>>3 (out row PAIR 2ty, 2ty+1).
// Smem tile staged as float2 row-pairs: tileP[r][c] = (x[row r], x[row r+1]),
// with the (kx0, ky0) window origin baked into the staging so compute
// addressing is origin-free. XOR swizzle for conflict-free LDS.64.
// Double-buffered so staging of channel c+1 overlaps compute of c.
// Inner math: packed fma.rn.f32x2 -> 2 fp32 FMAs per instruction.
// ---------------------------------------------------------------------------
#define TW 64
#define TH 64
#define SROWS 71              // row-pairs r = 0..70 (2*31+8 = 70 max)
#define SCOLS 72              // logical cols 0..71 (8*7+15 = 71 max)
#define SWP 73                // float2 row stride (odd)
#define TILE_ELEMS (SROWS * SCOLS)  // 5112
#define TILE_F2 (SROWS * SWP)       // 5183 float2 per buffer
#define SMEM_F2 (2 * TILE_F2 + 2 * WIN_ * WIN_)
#define SMEM_BYTES (SMEM_F2 * sizeof(float2))   // 84224 B

__device__ __forceinline__ void stage_channel(
        float2* __restrict__ tbuf, float2* __restrict__ wbuf,
        const float* __restrict__ xb, int o, int c,
        int i0, int j0, int tid) {
    const int g = o * NC_ + c;
    if (tid < WIN_ * WIN_) wbuf[tid] = g_w2[g * (WIN_ * WIN_) + tid];
    const int kx0 = g_kx0[g];
    const int ky0 = g_ky0[g];
    const float* __restrict__ xc = xb + (size_t)c * NXL * NYL;
    const int ri0 = i0 + kx0 - 8;
    const int cj0 = j0 + ky0 - 8;
#pragma unroll 5
    for (int idx = tid; idx < TILE_ELEMS; idx += 256) {
        int r  = idx / SCOLS;
        int cc = idx - r * SCOLS;
        int gi = ri0 + r;
        int gj = cj0 + cc;
        float v0 = 0.0f, v1 = 0.0f;
        if ((unsigned)gj < NYL) {
            if ((unsigned)gi < NXL)       v0 = xc[gi * NYL + gj];
            if ((unsigned)(gi + 1) < NXL) v1 = xc[(gi + 1) * NYL + gj];
        }
        int phys = (cc ^ (((cc >> 4) & 3) << 1)) ^ ((r >> 1) & 1);
        tbuf[r * SWP + phys] = make_float2(v0, v1);
    }
}

__global__ __launch_bounds__(256, 2) void conv_kernel(
        const float* __restrict__ x, float* __restrict__ out) {
    extern __shared__ float2 smem[];
    float2* tile0 = smem;
    float2* tile1 = smem + TILE_F2;
    float2* wp0   = smem + 2 * TILE_F2;
    float2* wp1   = wp0 + WIN_ * WIN_;

    const int tid = threadIdx.x;
    const int tx = tid & 7;
    const int ty = tid >> 3;          // 0..31 -> out rows 2ty, 2ty+1

    const int o = blockIdx.y;
    const int b = blockIdx.z;
    const int i0 = (blockIdx.x >> 2) * TH;  // 4 row tiles
    const int j0 = (blockIdx.x & 3) * TW;   // 4 col tiles

    // per-thread swizzled column offsets (row-parity applied per row)
    int q[16];
#pragma unroll
    for (int k = 0; k < 16; ++k) {
        int cc = tx * 8 + k;
        q[k] = cc ^ (((cc >> 4) & 3) << 1);
    }

    const float* __restrict__ xb = x + (size_t)b * NC_ * NXL * NYL;

    ull acc[8];
#pragma unroll
    for (int jj = 0; jj < 8; ++jj) acc[jj] = 0ull;

    stage_channel(tile0, wp0, xb, o, 0, i0, j0, tid);
    __syncthreads();

    for (int c = 0; c < NC_; ++c) {
        const float2* tcur = (c & 1) ? tile1 : tile0;
        const float2* wcur = (c & 1) ? wp1 : wp0;
        if (c + 1 < NC_)
            stage_channel((c & 1) ? tile0 : tile1, (c & 1) ? wp0 : wp1,
                          xb, o, c + 1, i0, j0, tid);

#pragma unroll
        for (int u = 0; u < WIN_; ++u) {
            const int r = 2 * ty + u;
            const float2* rowp = tcur + r * SWP;
            const int sig = (r >> 1) & 1;

            ull X[16];
#pragma unroll
            for (int k = 0; k < 16; ++k)
                X[k] = *(const ull*)(rowp + (q[k] ^ sig));

            ull w2[WIN_];
#pragma unroll
            for (int v = 0; v < WIN_; ++v)
                w2[v] = *(const ull*)(wcur + u * WIN_ + v);

#pragma unroll
            for (int v = 0; v < WIN_; ++v) {
#pragma unroll
                for (int jj = 0; jj < 8; ++jj)
                    asm("fma.rn.f32x2 %0, %1, %2, %0;"
                        : "+l"(acc[jj]) : "l"(X[v + jj]), "l"(w2[v]));
            }
        }
        __syncthreads();
    }

    // epilogue: unpack row pairs, write 2 rows x 8 cols as float4s
    const int orow = i0 + 2 * ty;
    float* op0 = out + ((size_t)(b * NO_ + o) * NXL + orow) * NYL + j0 + tx * 8;
    float* op1 = op0 + NYL;
    float lo[8], hi[8];
#pragma unroll
    for (int jj = 0; jj < 8; ++jj) {
        lo[jj] = __uint_as_float((unsigned)(acc[jj] & 0xffffffffull));
        hi[jj] = __uint_as_float((unsigned)(acc[jj] >> 32));
    }
    reinterpret_cast<float4*>(op0)[0] = make_float4(lo[0], lo[1], lo[2], lo[3]);
    reinterpret_cast<float4*>(op0)[1] = make_float4(lo[4], lo[5], lo[6], lo[7]);
    reinterpret_cast<float4*>(op1)[0] = make_float4(hi[0], hi[1], hi[2], hi[3]);
    reinterpret_cast<float4*>(op1)[1] = make_float4(hi[4], hi[5], hi[6], hi[7]);
}

// ---------------------------------------------------------------------------
extern "C" void kernel_launch(void* const* d_in, const int* in_sizes, int n_in,
                              void* d_out, int out_size) {
    const float* x   = (const float*)d_in[0];
    const float* vk  = (const float*)d_in[1];
    const int*   loc = (const int*)d_in[2];
    float* out = (float*)d_out;

    int nloc = in_sizes[2];
    int batch = in_sizes[0] / (NC_ * NXL * NYL);

    cudaFuncSetAttribute(conv_kernel,
                         cudaFuncAttributeMaxDynamicSharedMemorySize,
                         SMEM_BYTES);

    prep_kernel<<<1, 256>>>(vk, loc, nloc);

    dim3 grid((NXL / TH) * (NYL / TW), NO_, batch);  // (16, 3, 16)
    conv_kernel<<<grid, 256, SMEM_BYTES>>>(x, out);
}

// round 3
// speedup vs baseline: 1.6693x; 1.6693x over previous
#include <cuda_runtime.h>
#include <cuda_bf16.h>

typedef unsigned long long ull;

// Problem dims
#define B_   16
#define NC_  31
#define NXL  256
#define NYL  256
#define NO_  3
#define KXL  17
#define KYL  17
#define NG_  (NO_ * NC_)   // 93
#define WIN_ 9

// Compact weights: per (o,c) group a 9x9 tile of broadcast (v,v) float2 pairs
__device__ float2 g_w2[NG_ * WIN_ * WIN_];
__device__ int    g_kx0[NG_];
__device__ int    g_ky0[NG_];

// ---------------------------------------------------------------------------
// Prep: decode locations, find window origin per group, scatter relu(values)
// as broadcast (v,v) pairs. Single block; syncthreads orders phases.
// ---------------------------------------------------------------------------
__global__ void prep_kernel(const float* __restrict__ vk,
                            const int* __restrict__ loc, int nloc) {
    int tid = threadIdx.x;
    for (int i = tid; i < NG_; i += blockDim.x) {
        g_kx0[i] = 1 << 30;
        g_ky0[i] = 1 << 30;
    }
    __syncthreads();
    for (int i = tid; i < nloc; i += blockDim.x) {
        int idx = loc[i];
        int ky = idx % KYL; int t = idx / KYL;
        int kx = t % KXL;   t /= KXL;
        atomicMin(&g_kx0[t], kx);
        atomicMin(&g_ky0[t], ky);
    }
    __syncthreads();
    for (int i = tid; i < nloc; i += blockDim.x) {
        int idx = loc[i];
        float v = vk[i];
        v = v > 0.0f ? v : 0.0f;  // ReLU
        int ky = idx % KYL; int t = idx / KYL;
        int kx = t % KXL;   t /= KXL;
        g_w2[t * (WIN_ * WIN_) + (kx - g_kx0[t]) * WIN_ + (ky - g_ky0[t])] =
            make_float2(v, v);
    }
}

// ---------------------------------------------------------------------------
// Main conv. Block = 256 threads, output tile 32 rows x 128 cols per (b,o).
// Thread: tx = tid&7 (8 groups of 16 cols), ty = tid>>3 (32 rows).
// Scalar input tile in smem, 16B-unit XOR swizzle -> near-conflict-free
// LDS.128. Window origin (kx0,ky0) baked into staging. Inner math is packed
// fma.rn.f32x2 with dual-phase accumulators (accA even taps, accB odd taps
// shifted one column) so ALL operand pairs are aligned loads - no packing.
// Channel c+1 is prefetched into registers during compute of c (double buffer,
// one __syncthreads per channel).
// ---------------------------------------------------------------------------
#define TH 32          // out tile rows
#define TW 128         // out tile cols
#define SRO 40         // staged rows (TH + 8)
#define SCC 136        // staged logical cols (TW + 8)
#define SWF 160        // smem row stride in floats (40 16B units, swizzle room)
#define STAGE_N (SRO * SCC)              // 5440
#define NLDV 22                          // ceil(5440/256)
#define TILE_F (SRO * SWF)               // 6400 floats per buffer
#define WPAD 10                          // padded weight row stride (ull)
#define WBUF (WIN_ * WPAD)               // 90 ull per buffer
#define SMEM_BYTES (2 * TILE_F * 4 + 2 * WBUF * 8)   // 52640

__device__ __forceinline__ int swz_unit(int cu) {
    return cu ^ ((cu >> 3) & 7);
}

__global__ void __launch_bounds__(256, 2) conv_kernel(
        const float* __restrict__ x, float* __restrict__ out) {
    extern __shared__ float smem[];
    float* buf[2] = { smem, smem + TILE_F };
    ull* wbuf[2] = { (ull*)(smem + 2 * TILE_F),
                     (ull*)(smem + 2 * TILE_F) + WBUF };

    const int tid = threadIdx.x;
    const int tx = tid & 7;        // 16-col group
    const int ty = tid >> 3;       // output row 0..31

    const int o = blockIdx.y;
    const int b = blockIdx.z;
    const int i0 = (blockIdx.x >> 1) * TH;  // 8 row tiles
    const int j0 = (blockIdx.x & 1) * TW;   // 2 col tiles

    // per-thread swizzled float offsets for the 6 LDS.128 (row-independent)
    int puoff[6];
#pragma unroll
    for (int k = 0; k < 6; ++k) puoff[k] = swz_unit(4 * tx + k) << 2;

    const float* __restrict__ xb = x + (size_t)b * NC_ * NXL * NYL;

    // ---- stage channel 0 directly ----
    {
        const int g = o * NC_;
        const int ri0 = i0 + g_kx0[g] - 8;
        const int cj0 = j0 + g_ky0[g] - 8;
        const float* __restrict__ xc = xb;
#pragma unroll
        for (int l = 0; l < NLDV; ++l) {
            int idx = tid + 256 * l;
            if (idx < STAGE_N) {
                int r  = idx / SCC;
                int cc = idx - r * SCC;
                int gi = ri0 + r, gj = cj0 + cc;
                float v = 0.0f;
                if ((unsigned)gi < NXL && (unsigned)gj < NYL)
                    v = xc[gi * NYL + gj];
                buf[0][r * SWF + ((swz_unit(cc >> 2) << 2) | (cc & 3))] = v;
            }
        }
        if (tid < WIN_ * WIN_)
            wbuf[0][(tid / WIN_) * WPAD + tid % WIN_] =
                ((const ull*)g_w2)[g * (WIN_ * WIN_) + tid];
    }
    __syncthreads();

    // accA[j] = (out[2j], out[2j+1]); accB[i] = (out[2i-1], out[2i])
    ull accA[8], accB[9];
#pragma unroll
    for (int j = 0; j < 8; ++j) accA[j] = 0ull;
#pragma unroll
    for (int i = 0; i < 9; ++i) accB[i] = 0ull;

    for (int c = 0; c < NC_; ++c) {
        const float* tcur = buf[c & 1];
        const ull*   wcur = wbuf[c & 1];

        // ---- prefetch channel c+1 into registers (LDG overlaps compute) ----
        float vals[NLDV];
        ull wval = 0;
        const bool more = (c + 1 < NC_);
        if (more) {
            const int g = o * NC_ + c + 1;
            const int ri0 = i0 + g_kx0[g] - 8;
            const int cj0 = j0 + g_ky0[g] - 8;
            const float* __restrict__ xc = xb + (size_t)(c + 1) * NXL * NYL;
#pragma unroll
            for (int l = 0; l < NLDV; ++l) {
                int idx = tid + 256 * l;
                float v = 0.0f;
                if (idx < STAGE_N) {
                    int r  = idx / SCC;
                    int cc = idx - r * SCC;
                    int gi = ri0 + r, gj = cj0 + cc;
                    if ((unsigned)gi < NXL && (unsigned)gj < NYL)
                        v = xc[gi * NYL + gj];
                }
                vals[l] = v;
            }
            if (tid < WIN_ * WIN_)
                wval = ((const ull*)g_w2)[g * (WIN_ * WIN_) + tid];
        }

        // ---- compute channel c ----
#pragma unroll
        for (int u = 0; u < WIN_; ++u) {
            const float* rowp = tcur + (ty + u) * SWF;
            ull E[12];
#pragma unroll
            for (int k = 0; k < 6; ++k) {
                longlong2 L = *(const longlong2*)(rowp + puoff[k]);
                E[2 * k]     = (ull)L.x;
                E[2 * k + 1] = (ull)L.y;
            }
            const ull* wrow = wcur + u * WPAD;
            ull wu[WIN_];
#pragma unroll
            for (int v = 0; v < WIN_; ++v) wu[v] = wrow[v];

#pragma unroll
            for (int t = 0; t < 5; ++t) {        // even taps v = 2t
#pragma unroll
                for (int j = 0; j < 8; ++j)
                    asm("fma.rn.f32x2 %0, %1, %2, %0;"
                        : "+l"(accA[j]) : "l"(E[j + t]), "l"(wu[2 * t]));
                if (t < 4) {                      // odd taps v = 2t+1
#pragma unroll
                    for (int i = 0; i < 9; ++i)
                        asm("fma.rn.f32x2 %0, %1, %2, %0;"
                            : "+l"(accB[i]) : "l"(E[i + t]), "l"(wu[2 * t + 1]));
                }
            }
        }

        // ---- store prefetched channel c+1 ----
        if (more) {
            float* tnext = buf[(c + 1) & 1];
#pragma unroll
            for (int l = 0; l < NLDV; ++l) {
                int idx = tid + 256 * l;
                if (idx < STAGE_N) {
                    int r  = idx / SCC;
                    int cc = idx - r * SCC;
                    tnext[r * SWF + ((swz_unit(cc >> 2) << 2) | (cc & 3))] =
                        vals[l];
                }
            }
            if (tid < WIN_ * WIN_)
                wbuf[(c + 1) & 1][(tid / WIN_) * WPAD + tid % WIN_] = wval;
        }
        __syncthreads();
    }

    // ---- epilogue: merge dual-phase accumulators, write 16 cols ----
    float res[16];
#pragma unroll
    for (int j = 0; j < 8; ++j) {
        float aLo = __uint_as_float((unsigned)(accA[j] & 0xffffffffull));
        float aHi = __uint_as_float((unsigned)(accA[j] >> 32));
        float bHi = __uint_as_float((unsigned)(accB[j] >> 32));
        float bLo = __uint_as_float((unsigned)(accB[j + 1] & 0xffffffffull));
        res[2 * j]     = aLo + bHi;
        res[2 * j + 1] = aHi + bLo;
    }
    float* op = out + ((size_t)(b * NO_ + o) * NXL + (i0 + ty)) * NYL
                    + j0 + tx * 16;
#pragma unroll
    for (int q = 0; q < 4; ++q)
        reinterpret_cast<float4*>(op)[q] =
            make_float4(res[4 * q], res[4 * q + 1],
                        res[4 * q + 2], res[4 * q + 3]);
}

// ---------------------------------------------------------------------------
extern "C" void kernel_launch(void* const* d_in, const int* in_sizes, int n_in,
                              void* d_out, int out_size) {
    const float* x   = (const float*)d_in[0];
    const float* vk  = (const float*)d_in[1];
    const int*   loc = (const int*)d_in[2];
    float* out = (float*)d_out;

    int nloc = in_sizes[2];
    int batch = in_sizes[0] / (NC_ * NXL * NYL);

    cudaFuncSetAttribute(conv_kernel,
                         cudaFuncAttributeMaxDynamicSharedMemorySize,
                         SMEM_BYTES);

    prep_kernel<<<1, 256>>>(vk, loc, nloc);

    dim3 grid((NXL / TH) * (NYL / TW), NO_, batch);  // (16, 3, 16)
    conv_kernel<<<grid, 256, SMEM_BYTES>>>(x, out);
}

// round 4
// speedup vs baseline: 2.0224x; 1.2116x over previous
#include <cuda_runtime.h>
#include <cuda_bf16.h>

typedef unsigned long long ull;

// Problem dims
#define B_   16
#define NC_  31
#define NXL  256
#define NYL  256
#define NO_  3
#define KXL  17
#define KYL  17
#define NG_  (NO_ * NC_)   // 93
#define WIN_ 9

// Compact weights: per (o,c) group a 9x9 tile of broadcast (v,v) float2 pairs
__device__ float2 g_w2[NG_ * WIN_ * WIN_];
__device__ int    g_kx0[NG_];
__device__ int    g_ky0[NG_];

// ---------------------------------------------------------------------------
// Prep: decode locations, find window origin per group, scatter relu(values)
// as broadcast (v,v) pairs. Single block; syncthreads orders phases.
// ---------------------------------------------------------------------------
__global__ void prep_kernel(const float* __restrict__ vk,
                            const int* __restrict__ loc, int nloc) {
    int tid = threadIdx.x;
    for (int i = tid; i < NG_; i += blockDim.x) {
        g_kx0[i] = 1 << 30;
        g_ky0[i] = 1 << 30;
    }
    __syncthreads();
    for (int i = tid; i < nloc; i += blockDim.x) {
        int idx = loc[i];
        int ky = idx % KYL; int t = idx / KYL;
        int kx = t % KXL;   t /= KXL;
        atomicMin(&g_kx0[t], kx);
        atomicMin(&g_ky0[t], ky);
    }
    __syncthreads();
    for (int i = tid; i < nloc; i += blockDim.x) {
        int idx = loc[i];
        float v = vk[i];
        v = v > 0.0f ? v : 0.0f;  // ReLU
        int ky = idx % KYL; int t = idx / KYL;
        int kx = t % KXL;   t /= KXL;
        g_w2[t * (WIN_ * WIN_) + (kx - g_kx0[t]) * WIN_ + (ky - g_ky0[t])] =
            make_float2(v, v);
    }
}

// ---------------------------------------------------------------------------
// Main conv. Block = 256 threads, output tile 32 rows x 128 cols per (b,o).
// Staging is pure cp.async (zero-fill for OOB padding) with structured
// per-thread addressing (thread owns rows {ty, ty+32}, cols tx+8k) - no
// divides, no register-held prefetch buffer. Double-buffered smem, one
// commit_group per channel, wait_group 0 + one __syncthreads per channel.
// Inner math: packed fma.rn.f32x2 with dual-phase accumulators (accA even
// taps, accB odd taps shifted one column) so all pairs come from aligned
// LDS.128 of the XOR-swizzled tile. Weights loaded JIT inside the tap loop.
// ---------------------------------------------------------------------------
#define TH 32          // out tile rows
#define TW 128         // out tile cols
#define SRO 40         // staged rows (TH + 8)
#define SCC 136        // staged logical cols (TW + 8)
#define SWF 160        // smem row stride in floats
#define TILE_F (SRO * SWF)               // 6400 floats per buffer
#define WPAD 10                          // padded weight row stride (ull)
#define WBUF (WIN_ * WPAD)               // 90 ull per buffer
#define SMEM_BYTES (2 * TILE_F * 4 + 2 * WBUF * 8 + NC_ * 4)  // 52764

__device__ __forceinline__ int swz_unit(int cu) {
    return cu ^ ((cu >> 3) & 7);
}

__global__ void __launch_bounds__(256, 3) conv_kernel(
        const float* __restrict__ x, float* __restrict__ out) {
    extern __shared__ float smem[];
    float* buf0 = smem;
    float* buf1 = smem + TILE_F;
    ull*   wb0  = (ull*)(smem + 2 * TILE_F);
    ull*   wb1  = wb0 + WBUF;
    int*   s_ori = (int*)(wb1 + WBUF);

    const int tid = threadIdx.x;
    const int tx = tid & 7;        // 16-col group
    const int ty = tid >> 3;       // output row 0..31

    const int o = blockIdx.y;
    const int b = blockIdx.z;
    const int i0 = (blockIdx.x >> 1) * TH;  // 8 row tiles
    const int j0 = (blockIdx.x & 1) * TW;   // 2 col tiles

    // preload per-channel window origins for this order into smem
    if (tid < NC_)
        s_ori[tid] = (g_kx0[o * NC_ + tid] << 8) | g_ky0[o * NC_ + tid];
    __syncthreads();

    const unsigned sb0 = (unsigned)__cvta_generic_to_shared(buf0);
    const unsigned sb1 = (unsigned)__cvta_generic_to_shared(buf1);
    const unsigned wbu0 = (unsigned)__cvta_generic_to_shared(wb0);
    const unsigned wbu1 = (unsigned)__cvta_generic_to_shared(wb1);

    const float* __restrict__ xb = x + (size_t)b * NC_ * NXL * NYL;
    const int txq = tx >> 2, tx3 = tx & 3;

    // ---- async staging of one channel into buffer sel ----
    auto stage = [&](int c, int sel) {
        const int ori = s_ori[c];
        const int ky0 = ori & 255;
        const int kx0 = ori >> 8;
        const float* __restrict__ xc = xb + (size_t)c * NXL * NYL;
        const int ri0 = i0 + kx0 - 8;
        const int cj0 = j0 + ky0 - 8;
        const unsigned sbase = sel ? sb1 : sb0;
#pragma unroll
        for (int pass = 0; pass < 2; ++pass) {
            const int r = ty + pass * 32;
            if (pass == 1 && ty >= 8) break;
            const int gi = ri0 + r;
            const bool rowok = (unsigned)gi < NXL;
            const float* gp = xc + gi * NYL + cj0 + tx;
            const unsigned sp = sbase + (unsigned)(r * SWF + tx3) * 4u;
#pragma unroll
            for (int k = 0; k < 17; ++k) {
                const int gj = cj0 + tx + 8 * k;
                const int ok = (rowok && (unsigned)gj < NYL) ? 4 : 0;
                const int cu = txq + 2 * k;
                const int sw = cu ^ ((cu >> 3) & 7);
                const unsigned dst = sp + ((unsigned)sw << 4);
                const float* src = ok ? (gp + 8 * k) : xc;  // clamp when zfill
                asm volatile("cp.async.ca.shared.global [%0], [%1], 4, %2;"
                             :: "r"(dst), "l"(src), "r"(ok) : "memory");
            }
        }
        if (tid < WIN_ * WIN_) {
            const unsigned wdst = (sel ? wbu1 : wbu0)
                + (unsigned)((tid / WIN_) * WPAD + tid % WIN_) * 8u;
            const ull* wsrc = ((const ull*)g_w2)
                + (size_t)(o * NC_ + c) * (WIN_ * WIN_) + tid;
            asm volatile("cp.async.ca.shared.global [%0], [%1], 8;"
                         :: "r"(wdst), "l"(wsrc) : "memory");
        }
        asm volatile("cp.async.commit_group;" ::: "memory");
    };

    // per-thread swizzled float offsets for the 6 LDS.128 (row-independent)
    int puoff[6];
#pragma unroll
    for (int k = 0; k < 6; ++k) puoff[k] = swz_unit(4 * tx + k) << 2;

    // accA[j] = (out[2j], out[2j+1]); accB[i] = (out[2i-1], out[2i])
    ull accA[8], accB[9];
#pragma unroll
    for (int j = 0; j < 8; ++j) accA[j] = 0ull;
#pragma unroll
    for (int i = 0; i < 9; ++i) accB[i] = 0ull;

    stage(0, 0);

    for (int c = 0; c < NC_; ++c) {
        asm volatile("cp.async.wait_group 0;" ::: "memory");
        __syncthreads();
        if (c + 1 < NC_) stage(c + 1, (c + 1) & 1);

        const float* tcur = (c & 1) ? buf1 : buf0;
        const ull*   wcur = (c & 1) ? wb1 : wb0;

#pragma unroll
        for (int u = 0; u < WIN_; ++u) {
            const float* rowp = tcur + (ty + u) * SWF;
            ull E[12];
#pragma unroll
            for (int k = 0; k < 6; ++k) {
                longlong2 L = *(const longlong2*)(rowp + puoff[k]);
                E[2 * k]     = (ull)L.x;
                E[2 * k + 1] = (ull)L.y;
            }
            const ull* wrow = wcur + u * WPAD;
#pragma unroll
            for (int t = 0; t < 5; ++t) {        // even taps v = 2t
                const ull we = wrow[2 * t];
#pragma unroll
                for (int j = 0; j < 8; ++j)
                    asm("fma.rn.f32x2 %0, %1, %2, %0;"
                        : "+l"(accA[j]) : "l"(E[j + t]), "l"(we));
                if (t < 4) {                      // odd taps v = 2t+1
                    const ull wo = wrow[2 * t + 1];
#pragma unroll
                    for (int i = 0; i < 9; ++i)
                        asm("fma.rn.f32x2 %0, %1, %2, %0;"
                            : "+l"(accB[i]) : "l"(E[i + t]), "l"(wo));
                }
            }
        }
        __syncthreads();  // readers done before next channel's cp.async lands
    }

    // ---- epilogue: merge dual-phase accumulators, write 16 cols ----
    float res[16];
#pragma unroll
    for (int j = 0; j < 8; ++j) {
        float aLo = __uint_as_float((unsigned)(accA[j] & 0xffffffffull));
        float aHi = __uint_as_float((unsigned)(accA[j] >> 32));
        float bHi = __uint_as_float((unsigned)(accB[j] >> 32));
        float bLo = __uint_as_float((unsigned)(accB[j + 1] & 0xffffffffull));
        res[2 * j]     = aLo + bHi;
        res[2 * j + 1] = aHi + bLo;
    }
    float* op = out + ((size_t)(b * NO_ + o) * NXL + (i0 + ty)) * NYL
                    + j0 + tx * 16;
#pragma unroll
    for (int q = 0; q < 4; ++q)
        reinterpret_cast<float4*>(op)[q] =
            make_float4(res[4 * q], res[4 * q + 1],
                        res[4 * q + 2], res[4 * q + 3]);
}

// ---------------------------------------------------------------------------
extern "C" void kernel_launch(void* const* d_in, const int* in_sizes, int n_in,
                              void* d_out, int out_size) {
    const float* x   = (const float*)d_in[0];
    const float* vk  = (const float*)d_in[1];
    const int*   loc = (const int*)d_in[2];
    float* out = (float*)d_out;

    int nloc = in_sizes[2];
    int batch = in_sizes[0] / (NC_ * NXL * NYL);

    cudaFuncSetAttribute(conv_kernel,
                         cudaFuncAttributeMaxDynamicSharedMemorySize,
                         SMEM_BYTES);

    prep_kernel<<<1, 256>>>(vk, loc, nloc);

    dim3 grid((NXL / TH) * (NYL / TW), NO_, batch);  // (16, 3, 16)
    conv_kernel<<<grid, 256, SMEM_BYTES>>>(x, out);
}